// round 11
// baseline (speedup 1.0000x reference)
#include <cuda_runtime.h>

#define N_PIX 87040

// ---- shared pool (worst case TS=64): lum 76*84 + hT 64*76 + sx64 + sy64 ----
#define POOL_FLOATS (76 * 84 + 64 * 76 + 128)

// 24-float window (phase 2): element m (0..23) -> output j (0..7), tap T[|m-8-j|] if <=6
#define CONTRIB8(vv, m)                                                          \
    { if ((m) >= 2  && (m) <= 14) o0 += T[(m) >= 8  ? (m)-8  : 8-(m)]  * (vv);   \
      if ((m) >= 3  && (m) <= 15) o1 += T[(m) >= 9  ? (m)-9  : 9-(m)]  * (vv);   \
      if ((m) >= 4  && (m) <= 16) o2 += T[(m) >= 10 ? (m)-10 : 10-(m)] * (vv);   \
      if ((m) >= 5  && (m) <= 17) o3 += T[(m) >= 11 ? (m)-11 : 11-(m)] * (vv);   \
      if ((m) >= 6  && (m) <= 18) o4 += T[(m) >= 12 ? (m)-12 : 12-(m)] * (vv);   \
      if ((m) >= 7  && (m) <= 19) o5 += T[(m) >= 13 ? (m)-13 : 13-(m)] * (vv);   \
      if ((m) >= 8  && (m) <= 20) o6 += T[(m) >= 14 ? (m)-14 : 14-(m)] * (vv);   \
      if ((m) >= 9  && (m) <= 21) o7 += T[(m) >= 15 ? (m)-15 : 15-(m)] * (vv); }

// 16-float window (phase 3a): element m (0..15) -> output j (0..3), tap T[|m-6-j|] if <=6
#define CONTRIB4(vv, m)                                                      \
    { if ((m) <= 12)              o0 += T[(m) >= 6 ? (m)-6 : 6-(m)] * (vv);  \
      if ((m) >= 1 && (m) <= 13)  o1 += T[(m) >= 7 ? (m)-7 : 7-(m)] * (vv);  \
      if ((m) >= 2 && (m) <= 14)  o2 += T[(m) >= 8 ? (m)-8 : 8-(m)] * (vv);  \
      if ((m) >= 3)               o3 += T[(m) >= 9 ? (m)-9 : 9-(m)] * (vv); }

// W = image width (=height), TS = tile size. Compile-time only.
template<int W, int TS>
__device__ __forceinline__ void run_tile(int tloc, const float* __restrict__ base,
                                         float* __restrict__ obase,
                                         float* __restrict__ pool, int tid)
{
    const float T[7] = { 1.0f, 0.94595947f, 0.80073740f, 0.60653066f,
                         0.41111229f, 0.24935220f, 0.13533528f };
    constexpr int TPR  = W / TS;           // tiles per row
    constexpr int LR   = TS + 12;          // lum rows (halo +-6)
    constexpr int LC   = TS + 16;          // lum cols used (px -8 .. TS+7)
    constexpr int LPAD = (TS == 64) ? 84 : 52;  // padded lum row stride

    float* lum = pool;                       // [LR][LPAD]
    float* hT  = pool + LR * LPAD;           // [TS][LR] transposed H-blur
    float* sxs = pool + LR * LPAD + TS * LR;
    float* sys = sxs + TS;
    float* inv = pool;                       // aliases lum (dead after P2): [TS][TS+1]

    const int tx0 = (tloc & (TPR - 1)) * TS;
    const int ty0 = (tloc / TPR) * TS;

    // ---- dens tables ----
    if (tid < 2 * TS) {
        int p = tid & (TS - 1);
        int g = (tid < TS ? tx0 : ty0) + p;
        float s = T[0];
        s += (g >= 1 ? T[1] : 0.f) + (g >= 2 ? T[2] : 0.f) + (g >= 3 ? T[3] : 0.f)
           + (g >= 4 ? T[4] : 0.f) + (g >= 5 ? T[5] : 0.f) + (g >= 6 ? T[6] : 0.f);
        int d = W - 1 - g;
        s += (d >= 1 ? T[1] : 0.f) + (d >= 2 ? T[2] : 0.f) + (d >= 3 ? T[3] : 0.f)
           + (d >= 4 ? T[4] : 0.f) + (d >= 5 ? T[5] : 0.f) + (d >= 6 ? T[6] : 0.f);
        if (tid < TS) sxs[p] = s; else sys[p] = s;
    }

    // ---- phase 1: warp-cooperative AoS luminance gather ----
    // A warp handles a 30-float4 chunk (40 pixels, 480B contiguous) of one lum row.
    // lane <-> float4; class = lane % 3 is FIXED (30 ≡ 0 mod 3). One shfl_down
    // passes the cross-lane pixel partial. Coalesced LDG.128, scalar STS (1 writer/px).
    {
        constexpr int F4R = 3 * LC / 4;          // float4 per lum row (60 / 36)
        constexpr int NCH = LR * 2;              // 30-f4 chunks per tile
        constexpr int HI  = 3 * W * W - 4;
        const int warp = tid >> 5;
        const int lane = tid & 31;
        const int cls  = lane % 3;
        const int j4   = (lane < 30) ? (lane / 3) : 0;
        const bool interior = (tx0 >= 8) && (ty0 >= 6) &&
                              (tx0 + TS + 8 <= W) && (ty0 + TS + 6 <= W);
        for (int wi = warp; wi < NCH; wi += 16) {
            int r = wi >> 1;
            int c = wi & 1;
            int q = c * 30 + lane;               // float4 index within row
            bool act = (lane < 30) && (q < F4R);
            int gy = ty0 - 6 + r;
            int u  = (gy * W + tx0 - 8) * 3 + 4 * q;   // 16B-aligned
            int uc = min(max(u, 0), HI);
            float4 v = *(const float4*)(base + uc);

            float full = 0.f, contribA = 0.f, ownB = 0.f;
            if (cls == 0) {
                full = 0.2989f * v.x + 0.587f * v.y + 0.114f * v.z;
                ownB = 0.2989f * v.w;                       // R of pixel pb+1
            } else if (cls == 1) {
                contribA = 0.587f * v.x + 0.114f * v.y;     // G,B of pixel pb+1
                ownB     = 0.2989f * v.z + 0.587f * v.w;    // R,G of pixel pb+2
            } else {
                contribA = 0.114f * v.x;                    // B of pixel pb+2
                full     = 0.2989f * v.y + 0.587f * v.z + 0.114f * v.w; // pixel pb+3
            }
            float nb = __shfl_down_sync(0xffffffffu, contribA, 1);

            int pb = c * 40 + 4 * j4;            // buffer col of 4-pixel group
            float* lrow = &lum[r * LPAD];
            if (act) {
                if (interior) {
                    if (cls == 0)      { lrow[pb] = full; lrow[pb + 1] = ownB + nb; }
                    else if (cls == 1) { lrow[pb + 2] = ownB + nb; }
                    else               { lrow[pb + 3] = full; }
                } else {
                    bool ry = (unsigned)gy < (unsigned)W;
                    int gx0 = tx0 - 8 + pb;
                    if (cls == 0) {
                        lrow[pb]     = (ry && (unsigned)(gx0)     < (unsigned)W) ? full : 0.f;
                        lrow[pb + 1] = (ry && (unsigned)(gx0 + 1) < (unsigned)W) ? (ownB + nb) : 0.f;
                    } else if (cls == 1) {
                        lrow[pb + 2] = (ry && (unsigned)(gx0 + 2) < (unsigned)W) ? (ownB + nb) : 0.f;
                    } else {
                        lrow[pb + 3] = (ry && (unsigned)(gx0 + 3) < (unsigned)W) ? full : 0.f;
                    }
                }
            }
        }
    }
    __syncthreads();

    // ---- phase 2: horizontal blur; 8 outputs/thread via 6 aligned LDS.128 ----
    // outputs px cols 8g..8g+7 need buffer cols 8g+2..8g+21  (subset of [8g, 8g+24))
    {
        constexpr int NG = TS / 8;
        constexpr int NT = NG * LR;
        for (int t = tid; t < NT; t += 512) {
            int g = t / LR;
            int r = t - g * LR;
            const float* row = &lum[r * LPAD + g * 8];
            float o0 = 0.f, o1 = 0.f, o2 = 0.f, o3 = 0.f;
            float o4 = 0.f, o5 = 0.f, o6 = 0.f, o7 = 0.f;
#pragma unroll
            for (int k = 0; k < 6; k++) {
                float4 qv = *(const float4*)(row + 4 * k);
                CONTRIB8(qv.x, 4 * k + 0);
                CONTRIB8(qv.y, 4 * k + 1);
                CONTRIB8(qv.z, 4 * k + 2);
                CONTRIB8(qv.w, 4 * k + 3);
            }
            float* dst = &hT[(g * 8) * LR + r];   // transposed
            dst[0 * LR] = o0; dst[1 * LR] = o1; dst[2 * LR] = o2; dst[3 * LR] = o3;
            dst[4 * LR] = o4; dst[5 * LR] = o5; dst[6 * LR] = o6; dst[7 * LR] = o7;
        }
    }
    __syncthreads();

    // ---- phase 3a: vertical blur, 4 rows/thread via 4 LDS.128; dens; inv -> pool ----
    {
        constexpr int NT = TS * (TS / 4);
        for (int t = tid; t < NT; t += 512) {
            int c  = t & (TS - 1);
            int r0 = (t / TS) << 2;
            const float* colp = &hT[c * LR + r0];   // LR mult of 4 -> 16B aligned
            float o0 = 0.f, o1 = 0.f, o2 = 0.f, o3 = 0.f;
#pragma unroll
            for (int k = 0; k < 4; k++) {
                float4 qv = *(const float4*)(colp + 4 * k);
                CONTRIB4(qv.x, 4 * k + 0);
                CONTRIB4(qv.y, 4 * k + 1);
                CONTRIB4(qv.z, 4 * k + 2);
                CONTRIB4(qv.w, 4 * k + 3);
            }
            const float sx = sxs[c];
            float* invp = &inv[r0 * (TS + 1) + c];
            float a0 = 0.9999f * sys[r0 + 0] * sx;
            float a1 = 0.9999f * sys[r0 + 1] * sx;
            float a2 = 0.9999f * sys[r0 + 2] * sx;
            float a3 = 0.9999f * sys[r0 + 3] * sx;
            invp[0 * (TS + 1)] = __fdividef(a0, o0 + 1e-3f * a0);
            invp[1 * (TS + 1)] = __fdividef(a1, o1 + 1e-3f * a1);
            invp[2 * (TS + 1)] = __fdividef(a2, o2 + 1e-3f * a2);
            invp[3 * (TS + 1)] = __fdividef(a3, o3 + 1e-3f * a3);
        }
    }
    __syncthreads();

    // ---- phase 3b: vectorized divide; TS rows x (TS*3/4) float4 ----
    {
        constexpr int FPR = TS * 3 / 4;       // float4 per tile row (48 or 24)
        constexpr int NT  = TS * FPR;
        for (int t = tid; t < NT; t += 512) {
            int row = (TS == 64) ? (((t >> 4) * 21846) >> 16)    // t/48
                                 : (((t >> 3) * 21846) >> 16);   // t/24
            int f   = t - row * FPR;
            int u   = f << 2;
            int p0  = (u * 21846) >> 16;      // u/3 (exact, u <= 188)
            int fm3 = u - 3 * p0;
            int th  = 3 - fm3;

            const float* invrow = &inv[row * (TS + 1)];
            float iA = invrow[p0];
            float iB = invrow[p0 + 1];

            int goff = ((ty0 + row) * W + tx0) * 3 + u;
            float4 qv = *(const float4*)(base + goff);
            qv.x *= iA;
            qv.y *= (1 < th) ? iA : iB;
            qv.z *= (2 < th) ? iA : iB;
            qv.w *= iB;
            *(float4*)(obase + goff) = qv;
        }
    }
}

__global__ __launch_bounds__(512, 4)
void lln_kernel(const float* __restrict__ x, float* __restrict__ out)
{
    __shared__ float pool[POOL_FLOATS];
    const int tile = blockIdx.x;   // 0..21
    const int b    = blockIdx.y;
    const int tid  = threadIdx.x;
    const int bo   = b * (N_PIX * 3);

    if (tile < 16) {
        run_tile<256, 64>(tile,      x + bo,             out + bo,             pool, tid);
    } else if (tile < 20) {
        run_tile<128, 64>(tile - 16, x + bo + 65536 * 3, out + bo + 65536 * 3, pool, tid);
    } else if (tile == 20) {
        run_tile<64, 64> (0,         x + bo + 81920 * 3, out + bo + 81920 * 3, pool, tid);
    } else {
        run_tile<32, 32> (0,         x + bo + 86016 * 3, out + bo + 86016 * 3, pool, tid);
    }
}

extern "C" void kernel_launch(void* const* d_in, const int* in_sizes, int n_in,
                              void* d_out, int out_size)
{
    const float* x = (const float*)d_in[0];
    float* out     = (float*)d_out;
    dim3 grid(22, 128);
    lln_kernel<<<grid, 512>>>(x, out);
}

// round 12
// speedup vs baseline: 1.3418x; 1.3418x over previous
#include <cuda_runtime.h>

#define N_PIX 87040

// ---- shared pool (worst case TS=64): lum 76*84 + hT 64*76 + sx64 + sy64 ----
#define POOL_FLOATS (76 * 84 + 64 * 76 + 128)

// phase 2 (32-float window, 16 outputs): element m -> output j iff j+2<=m<=j+14, tap T[|m-8-j|]
#define C16(vv, m)                                                                 \
    { if ((m) >= 2  && (m) <= 14) o0  += T[(m) >= 8  ? (m)-8  : 8-(m)]  * (vv);    \
      if ((m) >= 3  && (m) <= 15) o1  += T[(m) >= 9  ? (m)-9  : 9-(m)]  * (vv);    \
      if ((m) >= 4  && (m) <= 16) o2  += T[(m) >= 10 ? (m)-10 : 10-(m)] * (vv);    \
      if ((m) >= 5  && (m) <= 17) o3  += T[(m) >= 11 ? (m)-11 : 11-(m)] * (vv);    \
      if ((m) >= 6  && (m) <= 18) o4  += T[(m) >= 12 ? (m)-12 : 12-(m)] * (vv);    \
      if ((m) >= 7  && (m) <= 19) o5  += T[(m) >= 13 ? (m)-13 : 13-(m)] * (vv);    \
      if ((m) >= 8  && (m) <= 20) o6  += T[(m) >= 14 ? (m)-14 : 14-(m)] * (vv);    \
      if ((m) >= 9  && (m) <= 21) o7  += T[(m) >= 15 ? (m)-15 : 15-(m)] * (vv);    \
      if ((m) >= 10 && (m) <= 22) o8  += T[(m) >= 16 ? (m)-16 : 16-(m)] * (vv);    \
      if ((m) >= 11 && (m) <= 23) o9  += T[(m) >= 17 ? (m)-17 : 17-(m)] * (vv);    \
      if ((m) >= 12 && (m) <= 24) o10 += T[(m) >= 18 ? (m)-18 : 18-(m)] * (vv);    \
      if ((m) >= 13 && (m) <= 25) o11 += T[(m) >= 19 ? (m)-19 : 19-(m)] * (vv);    \
      if ((m) >= 14 && (m) <= 26) o12 += T[(m) >= 20 ? (m)-20 : 20-(m)] * (vv);    \
      if ((m) >= 15 && (m) <= 27) o13 += T[(m) >= 21 ? (m)-21 : 21-(m)] * (vv);    \
      if ((m) >= 16 && (m) <= 28) o14 += T[(m) >= 22 ? (m)-22 : 22-(m)] * (vv);    \
      if ((m) >= 17 && (m) <= 29) o15 += T[(m) >= 23 ? (m)-23 : 23-(m)] * (vv); }

// phase 3a (20-float window, 8 outputs): element m -> output j iff j<=m<=j+12, tap T[|m-6-j|]
#define C8V(vv, m)                                                                \
    { if ((m) <= 12)              o0 += T[(m) >= 6  ? (m)-6  : 6-(m)]  * (vv);    \
      if ((m) >= 1 && (m) <= 13)  o1 += T[(m) >= 7  ? (m)-7  : 7-(m)]  * (vv);    \
      if ((m) >= 2 && (m) <= 14)  o2 += T[(m) >= 8  ? (m)-8  : 8-(m)]  * (vv);    \
      if ((m) >= 3 && (m) <= 15)  o3 += T[(m) >= 9  ? (m)-9  : 9-(m)]  * (vv);    \
      if ((m) >= 4 && (m) <= 16)  o4 += T[(m) >= 10 ? (m)-10 : 10-(m)] * (vv);    \
      if ((m) >= 5 && (m) <= 17)  o5 += T[(m) >= 11 ? (m)-11 : 11-(m)] * (vv);    \
      if ((m) >= 6 && (m) <= 18)  o6 += T[(m) >= 12 ? (m)-12 : 12-(m)] * (vv);    \
      if ((m) >= 7 && (m) <= 19)  o7 += T[(m) >= 13 ? (m)-13 : 13-(m)] * (vv); }

// W = image width (=height), TS = tile size. Compile-time only.
template<int W, int TS>
__device__ __forceinline__ void run_tile(int tloc, const float* __restrict__ base,
                                         float* __restrict__ obase,
                                         float* __restrict__ pool, int tid)
{
    const float T[7] = { 1.0f, 0.94595947f, 0.80073740f, 0.60653066f,
                         0.41111229f, 0.24935220f, 0.13533528f };
    constexpr int TPR  = W / TS;           // tiles per row
    constexpr int LR   = TS + 12;          // lum rows (halo +-6)
    constexpr int LC   = TS + 16;          // lum cols used (px -8 .. TS+7)
    constexpr int LPAD = (TS == 64) ? 84 : 52;  // padded lum row stride
    constexpr int NQ   = LC / 4;           // 4-pixel groups per lum row

    float* lum = pool;                       // [LR][LPAD]
    float* hT  = pool + LR * LPAD;           // [TS][LR] transposed H-blur
    float* sxs = pool + LR * LPAD + TS * LR;
    float* sys = sxs + TS;
    float* inv = pool;                       // aliases lum (dead after P2): [TS][TS+1]

    const int tx0 = (tloc & (TPR - 1)) * TS;
    const int ty0 = (tloc / TPR) * TS;

    // ---- dens tables ----
    if (tid < 2 * TS) {
        int p = tid & (TS - 1);
        int g = (tid < TS ? tx0 : ty0) + p;
        float s = T[0];
        s += (g >= 1 ? T[1] : 0.f) + (g >= 2 ? T[2] : 0.f) + (g >= 3 ? T[3] : 0.f)
           + (g >= 4 ? T[4] : 0.f) + (g >= 5 ? T[5] : 0.f) + (g >= 6 ? T[6] : 0.f);
        int d = W - 1 - g;
        s += (d >= 1 ? T[1] : 0.f) + (d >= 2 ? T[2] : 0.f) + (d >= 3 ? T[3] : 0.f)
           + (d >= 4 ? T[4] : 0.f) + (d >= 5 ? T[5] : 0.f) + (d >= 6 ? T[6] : 0.f);
        if (tid < TS) sxs[p] = s; else sys[p] = s;
    }

    // ---- phase 1 (R10 proven): task = 4 pixels (3 float4), row-major ----
    {
        constexpr int NT = LR * NQ;
        const bool interior = (tx0 >= 8) && (ty0 >= 6) &&
                              (tx0 + TS + 8 <= W) && (ty0 + TS + 6 <= W);
        int r = tid / NQ;
        int q = tid - r * NQ;
        constexpr int DR = 512 / NQ;
        constexpr int DQ = 512 - DR * NQ;
        if (interior) {
            for (int t = tid; t < NT; t += 512) {
                int u = ((ty0 - 6 + r) * W + tx0 - 8) * 3 + q * 12;
                float4 a = *(const float4*)(base + u);
                float4 b = *(const float4*)(base + u + 4);
                float4 c = *(const float4*)(base + u + 8);
                float4 o;
                o.x = 0.2989f * a.x + 0.587f * a.y + 0.114f * a.z;
                o.y = 0.2989f * a.w + 0.587f * b.x + 0.114f * b.y;
                o.z = 0.2989f * b.z + 0.587f * b.w + 0.114f * c.x;
                o.w = 0.2989f * c.y + 0.587f * c.z + 0.114f * c.w;
                *(float4*)&lum[r * LPAD + q * 4] = o;
                q += DQ; r += DR;
                if (q >= NQ) { q -= NQ; r += 1; }
            }
        } else {
            constexpr int HI = 3 * W * W - 4;
            for (int t = tid; t < NT; t += 512) {
                int gy  = ty0 - 6 + r;
                int gx0 = tx0 - 8 + q * 4;
                int u = (gy * W + gx0) * 3;
                int u0 = min(max(u,     0), HI);
                int u1 = min(max(u + 4, 0), HI);
                int u2 = min(max(u + 8, 0), HI);
                float4 a = *(const float4*)(base + u0);
                float4 b = *(const float4*)(base + u1);
                float4 c = *(const float4*)(base + u2);
                bool ry = (unsigned)gy < (unsigned)W;
                float4 o;
                o.x = (ry && (unsigned)(gx0    ) < (unsigned)W) ? (0.2989f * a.x + 0.587f * a.y + 0.114f * a.z) : 0.f;
                o.y = (ry && (unsigned)(gx0 + 1) < (unsigned)W) ? (0.2989f * a.w + 0.587f * b.x + 0.114f * b.y) : 0.f;
                o.z = (ry && (unsigned)(gx0 + 2) < (unsigned)W) ? (0.2989f * b.z + 0.587f * b.w + 0.114f * c.x) : 0.f;
                o.w = (ry && (unsigned)(gx0 + 3) < (unsigned)W) ? (0.2989f * c.y + 0.587f * c.z + 0.114f * c.w) : 0.f;
                *(float4*)&lum[r * LPAD + q * 4] = o;
                q += DQ; r += DR;
                if (q >= NQ) { q -= NQ; r += 1; }
            }
        }
    }
    __syncthreads();

    // ---- phase 2: horizontal blur; 16 outputs/thread via 8 aligned LDS.128 ----
    // outputs px cols 16g..16g+15 need buffer cols [16g+2, 16g+29] c aligned span [16g, 16g+32)
    {
        constexpr int NG = TS / 16;
        constexpr int NT = NG * LR;
        for (int t = tid; t < NT; t += 512) {
            int g = t / LR;
            int r = t - g * LR;
            const float* row = &lum[r * LPAD + g * 16];
            float o0  = 0.f, o1  = 0.f, o2  = 0.f, o3  = 0.f;
            float o4  = 0.f, o5  = 0.f, o6  = 0.f, o7  = 0.f;
            float o8  = 0.f, o9  = 0.f, o10 = 0.f, o11 = 0.f;
            float o12 = 0.f, o13 = 0.f, o14 = 0.f, o15 = 0.f;
#pragma unroll
            for (int k = 0; k < 8; k++) {
                float4 qv = *(const float4*)(row + 4 * k);
                C16(qv.x, 4 * k + 0);
                C16(qv.y, 4 * k + 1);
                C16(qv.z, 4 * k + 2);
                C16(qv.w, 4 * k + 3);
            }
            float* dst = &hT[(g * 16) * LR + r];   // transposed
            dst[ 0 * LR] = o0;  dst[ 1 * LR] = o1;  dst[ 2 * LR] = o2;  dst[ 3 * LR] = o3;
            dst[ 4 * LR] = o4;  dst[ 5 * LR] = o5;  dst[ 6 * LR] = o6;  dst[ 7 * LR] = o7;
            dst[ 8 * LR] = o8;  dst[ 9 * LR] = o9;  dst[10 * LR] = o10; dst[11 * LR] = o11;
            dst[12 * LR] = o12; dst[13 * LR] = o13; dst[14 * LR] = o14; dst[15 * LR] = o15;
        }
    }
    __syncthreads();

    // ---- phase 3a: vertical blur; 8 rows/thread via 5 aligned LDS.128; dens ----
    {
        constexpr int NT = TS * (TS / 8);
        for (int t = tid; t < NT; t += 512) {
            int c  = t & (TS - 1);
            int r0 = (t / TS) << 3;
            const float* colp = &hT[c * LR + r0];   // 16B aligned
            float o0 = 0.f, o1 = 0.f, o2 = 0.f, o3 = 0.f;
            float o4 = 0.f, o5 = 0.f, o6 = 0.f, o7 = 0.f;
#pragma unroll
            for (int k = 0; k < 5; k++) {
                float4 qv = *(const float4*)(colp + 4 * k);
                C8V(qv.x, 4 * k + 0);
                C8V(qv.y, 4 * k + 1);
                C8V(qv.z, 4 * k + 2);
                C8V(qv.w, 4 * k + 3);
            }
            const float sx = sxs[c];
            float* invp = &inv[r0 * (TS + 1) + c];
#pragma unroll
            for (int j = 0; j < 8; j++) {
                float oj = (j == 0) ? o0 : (j == 1) ? o1 : (j == 2) ? o2 : (j == 3) ? o3
                         : (j == 4) ? o4 : (j == 5) ? o5 : (j == 6) ? o6 : o7;
                float dj = 0.9999f * sys[r0 + j] * sx;
                invp[j * (TS + 1)] = __fdividef(dj, oj + 1e-3f * dj);
            }
        }
    }
    __syncthreads();

    // ---- phase 3b: vectorized divide; TS rows x (TS*3/4) float4 ----
    {
        constexpr int FPR = TS * 3 / 4;       // float4 per tile row (48 or 24)
        constexpr int NT  = TS * FPR;
        for (int t = tid; t < NT; t += 512) {
            int row = (TS == 64) ? (((t >> 4) * 21846) >> 16)    // t/48
                                 : (((t >> 3) * 21846) >> 16);   // t/24
            int f   = t - row * FPR;
            int u   = f << 2;
            int p0  = (u * 21846) >> 16;      // u/3 (exact, u <= 188)
            int fm3 = u - 3 * p0;
            int th  = 3 - fm3;

            const float* invrow = &inv[row * (TS + 1)];
            float iA = invrow[p0];
            float iB = invrow[p0 + 1];

            int goff = ((ty0 + row) * W + tx0) * 3 + u;
            float4 qv = *(const float4*)(base + goff);
            qv.x *= iA;
            qv.y *= (1 < th) ? iA : iB;
            qv.z *= (2 < th) ? iA : iB;
            qv.w *= iB;
            *(float4*)(obase + goff) = qv;
        }
    }
}

__global__ __launch_bounds__(512, 4)
void lln_kernel(const float* __restrict__ x, float* __restrict__ out)
{
    __shared__ float pool[POOL_FLOATS];
    const int tile = blockIdx.x;   // 0..21
    const int b    = blockIdx.y;
    const int tid  = threadIdx.x;
    const int bo   = b * (N_PIX * 3);

    if (tile < 16) {
        run_tile<256, 64>(tile,      x + bo,             out + bo,             pool, tid);
    } else if (tile < 20) {
        run_tile<128, 64>(tile - 16, x + bo + 65536 * 3, out + bo + 65536 * 3, pool, tid);
    } else if (tile == 20) {
        run_tile<64, 64> (0,         x + bo + 81920 * 3, out + bo + 81920 * 3, pool, tid);
    } else {
        run_tile<32, 32> (0,         x + bo + 86016 * 3, out + bo + 86016 * 3, pool, tid);
    }
}

extern "C" void kernel_launch(void* const* d_in, const int* in_sizes, int n_in,
                              void* d_out, int out_size)
{
    const float* x = (const float*)d_in[0];
    float* out     = (float*)d_out;
    dim3 grid(22, 128);
    lln_kernel<<<grid, 512>>>(x, out);
}